// round 2
// baseline (speedup 1.0000x reference)
#include <cuda_runtime.h>
#include <cuda_bf16.h>

#define NPTS     163840      // B*R*SR = 1*4096*40
#define KNEI     8
#define FDIM     32
#define HDIM     256
#define EPSV     1e-8f
#define MTILE    128
#define AP       264         // act smem pitch (bf16 elems): 528B rows -> 4-bank shift/row
#define WP       264         // weight smem pitch
#define NTHREADS 512
#define SMEM_BYTES ((MTILE*AP + HDIM*WP) * 2 + HDIM * 4)

// -------- device scratch (no allocations allowed) --------
__device__ __nv_bfloat16 g_feat[(size_t)NPTS * FDIM];   // aggregated features, bf16
__device__ __nv_bfloat16 g_w1a[HDIM * FDIM];            // W^T [out][in], bf16
__device__ __nv_bfloat16 g_w1b[HDIM * HDIM];
__device__ __nv_bfloat16 g_w3a[HDIM * HDIM];
__device__ __nv_bfloat16 g_w3b[HDIM * HDIM];

// ============================================================
// Kernel 1: transpose weights [in][out] -> [out][in] and cast to bf16
// ============================================================
__global__ void convert_weights_kernel(const float* __restrict__ W1a,
                                       const float* __restrict__ W1b,
                                       const float* __restrict__ W3a,
                                       const float* __restrict__ W3b) {
    int idx = blockIdx.x * blockDim.x + threadIdx.x;
    if (idx < HDIM * FDIM) {
        int o = idx / FDIM, i = idx - o * FDIM;
        g_w1a[idx] = __float2bfloat16(W1a[i * HDIM + o]);
    }
    if (idx < HDIM * HDIM) {
        int o = idx / HDIM, i = idx - o * HDIM;
        g_w1b[idx] = __float2bfloat16(W1b[i * HDIM + o]);
        g_w3a[idx] = __float2bfloat16(W3a[i * HDIM + o]);
        g_w3b[idx] = __float2bfloat16(W3b[i * HDIM + o]);
    }
}

// ============================================================
// Kernel 2: aggregation. One warp per point, lane = feature index.
//   w_k = mask_k / max(|d_k|^2, eps);  w_k /= max(sum w, eps)
//   feat_f = sum_k w_k * emb[k][f]
// ============================================================
__global__ void prep_kernel(const float* __restrict__ emb,
                            const float* __restrict__ dists,
                            const int*   __restrict__ mask) {
    int gw   = (blockIdx.x * blockDim.x + threadIdx.x) >> 5;
    int lane = threadIdx.x & 31;
    if (gw >= NPTS) return;

    float w = 0.f;
    if (lane < KNEI) {
        const float* d = dists + (size_t)gw * (KNEI * 3) + lane * 3;
        float d0 = d[0], d1 = d[1], d2 = d[2];
        float n2 = d0 * d0 + d1 * d1 + d2 * d2;
        w = mask[(size_t)gw * KNEI + lane] ? (1.0f / fmaxf(n2, EPSV)) : 0.f;
    }
    float ws = w;
    #pragma unroll
    for (int o = 16; o > 0; o >>= 1) ws += __shfl_xor_sync(0xffffffffu, ws, o);
    w /= fmaxf(ws, EPSV);

    const float* e = emb + (size_t)gw * (KNEI * FDIM) + lane;
    float acc = 0.f;
    #pragma unroll
    for (int k = 0; k < KNEI; k++) {
        float wk = __shfl_sync(0xffffffffu, w, k);
        acc += wk * e[k * FDIM];
    }
    g_feat[(size_t)gw * FDIM + lane] = __float2bfloat16(acc);
}

// ============================================================
// Kernel 3: fused 4-layer MLP + heads. 128 rows per CTA, 512 threads.
// 16 warps as 4(m) x 4(n): each warp owns 32 rows x 64 cols of the output,
// i.e. 2 m-tiles x 8 n-tiles of mma.m16n8k16 (bf16 in, fp32 acc).
// Activations live in smem (in-place, barrier-separated read/write phases).
// ============================================================
__device__ __forceinline__ void run_layer(
    __nv_bfloat16* act, __nv_bfloat16* wsm, float* bsm,
    const __nv_bfloat16* __restrict__ gW, const float* __restrict__ bias,
    int K, int tid, int lane, int wm, int wn)
{
    // stage W^T [256][K] -> smem [256][WP]
    const int vpr = K >> 3;                       // uint4 per row
    for (int i = tid; i < HDIM * vpr; i += NTHREADS) {
        int r = i / vpr, s = i - r * vpr;
        *(uint4*)(wsm + r * WP + s * 8) = *(const uint4*)(gW + (size_t)r * K + s * 8);
    }
    if (tid < HDIM) bsm[tid] = bias[tid];
    __syncthreads();

    float acc[2][8][4];
    #pragma unroll
    for (int mt = 0; mt < 2; mt++)
        #pragma unroll
        for (int nt = 0; nt < 8; nt++)
            #pragma unroll
            for (int q = 0; q < 4; q++) acc[mt][nt][q] = 0.f;

    const int g  = lane >> 2;
    const int tq = lane & 3;
    for (int kt = 0; kt < (K >> 4); kt++) {
        int c = kt * 16 + tq * 2;
        unsigned a[2][4];
        #pragma unroll
        for (int mt = 0; mt < 2; mt++) {
            int r = wm * 32 + mt * 16 + g;
            a[mt][0] = *(const unsigned*)(act + r * AP + c);
            a[mt][1] = *(const unsigned*)(act + (r + 8) * AP + c);
            a[mt][2] = *(const unsigned*)(act + r * AP + c + 8);
            a[mt][3] = *(const unsigned*)(act + (r + 8) * AP + c + 8);
        }
        unsigned b[8][2];
        #pragma unroll
        for (int nt = 0; nt < 8; nt++) {
            int n = wn * 64 + nt * 8 + g;
            b[nt][0] = *(const unsigned*)(wsm + n * WP + c);
            b[nt][1] = *(const unsigned*)(wsm + n * WP + c + 8);
        }
        #pragma unroll
        for (int mt = 0; mt < 2; mt++)
            #pragma unroll
            for (int nt = 0; nt < 8; nt++)
                asm volatile(
                    "mma.sync.aligned.m16n8k16.row.col.f32.bf16.bf16.f32 "
                    "{%0,%1,%2,%3}, {%4,%5,%6,%7}, {%8,%9}, {%0,%1,%2,%3};\n"
                    : "+f"(acc[mt][nt][0]), "+f"(acc[mt][nt][1]),
                      "+f"(acc[mt][nt][2]), "+f"(acc[mt][nt][3])
                    : "r"(a[mt][0]), "r"(a[mt][1]), "r"(a[mt][2]), "r"(a[mt][3]),
                      "r"(b[nt][0]), "r"(b[nt][1]));
    }
    __syncthreads();   // all reads of act/wsm complete

    // bias + relu + bf16, write back in place
    #pragma unroll
    for (int mt = 0; mt < 2; mt++) {
        int r = wm * 32 + mt * 16 + g;
        #pragma unroll
        for (int nt = 0; nt < 8; nt++) {
            int col = wn * 64 + nt * 8 + tq * 2;
            float bz0 = bsm[col], bz1 = bsm[col + 1];
            __nv_bfloat162 v01 = __floats2bfloat162_rn(
                fmaxf(acc[mt][nt][0] + bz0, 0.f), fmaxf(acc[mt][nt][1] + bz1, 0.f));
            __nv_bfloat162 v23 = __floats2bfloat162_rn(
                fmaxf(acc[mt][nt][2] + bz0, 0.f), fmaxf(acc[mt][nt][3] + bz1, 0.f));
            *(__nv_bfloat162*)(act + r * AP + col)       = v01;
            *(__nv_bfloat162*)(act + (r + 8) * AP + col) = v23;
        }
    }
    __syncthreads();
}

__global__ void __launch_bounds__(NTHREADS, 1)
mlp_kernel(const float* __restrict__ b1a, const float* __restrict__ b1b,
           const float* __restrict__ b3a, const float* __restrict__ b3b,
           const float* __restrict__ Wa,  const float* __restrict__ ba,
           const float* __restrict__ Wc,  const float* __restrict__ bc,
           const float* __restrict__ viewdirs, float* __restrict__ out)
{
    extern __shared__ __nv_bfloat16 smem[];
    __nv_bfloat16* act = smem;                       // [128][AP]
    __nv_bfloat16* wsm = smem + MTILE * AP;          // [256][WP]
    float*         bsm = (float*)(smem + MTILE * AP + HDIM * WP);

    int tid = threadIdx.x;
    int lane = tid & 31, wid = tid >> 5;
    int wm = wid >> 2, wn = wid & 3;
    int row0 = blockIdx.x * MTILE;

    {   // stage feat tile: 128 rows x 32 bf16
        int r = tid >> 2, s = tid & 3;
        *(uint4*)(act + r * AP + s * 8) =
            *(const uint4*)(g_feat + (size_t)(row0 + r) * FDIM + s * 8);
    }
    __syncthreads();

    run_layer(act, wsm, bsm, g_w1a, b1a, FDIM, tid, lane, wm, wn);
    run_layer(act, wsm, bsm, g_w1b, b1b, HDIM, tid, lane, wm, wn);
    run_layer(act, wsm, bsm, g_w3a, b3a, HDIM, tid, lane, wm, wn);
    run_layer(act, wsm, bsm, g_w3b, b3b, HDIM, tid, lane, wm, wn);

    // ---- heads: alpha (256->1) + color (280->3), fp32 ----
    float* sWa = (float*)wsm;       // 256 floats (wsm is free now)
    float* sWc = sWa + HDIM;        // 840 floats, layout [280][3]
    for (int i = tid; i < HDIM;    i += NTHREADS) sWa[i] = Wa[i];
    for (int i = tid; i < 280 * 3; i += NTHREADS) sWc[i] = Wc[i];
    __syncthreads();

    int r = tid >> 2, t = tid & 3;                   // 4 threads per row
    const __nv_bfloat16* hr = act + r * AP;
    float sa = 0.f, c0 = 0.f, c1 = 0.f, c2 = 0.f;
    for (int k = t * 64; k < t * 64 + 64; k++) {
        float h = __bfloat162float(hr[k]);
        sa += h * sWa[k];
        c0 += h * sWc[k * 3 + 0];
        c1 += h * sWc[k * 3 + 1];
        c2 += h * sWc[k * 3 + 2];
    }
    if (t == 0) {   // viewdir positional encoding (exact fp32)
        const float* v = viewdirs + (size_t)(row0 + r) * 3;
        float vx = v[0], vy = v[1], vz = v[2];
        float inv = 1.f / fmaxf(sqrtf(vx * vx + vy * vy + vz * vz), EPSV);
        vx *= inv; vy *= inv; vz *= inv;
        #pragma unroll
        for (int i = 0; i < 4; i++) {
            float f = (float)(1 << i);
            float pe[6];
            pe[0] = sinf(vx * f); pe[1] = sinf(vy * f); pe[2] = sinf(vz * f);
            pe[3] = cosf(vx * f); pe[4] = cosf(vy * f); pe[5] = cosf(vz * f);
            #pragma unroll
            for (int j = 0; j < 6; j++) {
                const float* wrow = sWc + (HDIM + i * 6 + j) * 3;
                c0 += pe[j] * wrow[0];
                c1 += pe[j] * wrow[1];
                c2 += pe[j] * wrow[2];
            }
        }
    }
    #pragma unroll
    for (int o = 1; o < 4; o <<= 1) {
        sa += __shfl_xor_sync(0xffffffffu, sa, o);
        c0 += __shfl_xor_sync(0xffffffffu, c0, o);
        c1 += __shfl_xor_sync(0xffffffffu, c1, o);
        c2 += __shfl_xor_sync(0xffffffffu, c2, o);
    }
    if (t == 0) {
        float apre  = sa + ba[0] - 1.0f;
        float alpha = (apre > 20.f) ? apre : log1pf(expf(apre));
        float r0 = c0 + bc[0], r1 = c1 + bc[1], r2 = c2 + bc[2];
        const float sc = 1.0f + 2e-3f, sh = 1e-3f;
        float4 o4;
        o4.x = alpha;
        o4.y = sc / (1.f + expf(-r0)) - sh;
        o4.z = sc / (1.f + expf(-r1)) - sh;
        o4.w = sc / (1.f + expf(-r2)) - sh;
        *(float4*)(out + (size_t)(row0 + r) * 4) = o4;
    }
}

// ============================================================
extern "C" void kernel_launch(void* const* d_in, const int* in_sizes, int n_in,
                              void* d_out, int out_size) {
    const float* emb   = (const float*)d_in[0];
    const float* dists = (const float*)d_in[1];
    const float* vdirs = (const float*)d_in[2];
    const int*   mask  = (const int*)d_in[3];
    const float* W1a = (const float*)d_in[4];
    const float* b1a = (const float*)d_in[5];
    const float* W1b = (const float*)d_in[6];
    const float* b1b = (const float*)d_in[7];
    const float* W3a = (const float*)d_in[8];
    const float* b3a = (const float*)d_in[9];
    const float* W3b = (const float*)d_in[10];
    const float* b3b = (const float*)d_in[11];
    const float* Wa  = (const float*)d_in[12];
    const float* ba  = (const float*)d_in[13];
    const float* Wc  = (const float*)d_in[14];
    const float* bc  = (const float*)d_in[15];
    float* out = (float*)d_out;

    convert_weights_kernel<<<(HDIM * HDIM + 255) / 256, 256>>>(W1a, W1b, W3a, W3b);
    prep_kernel<<<NPTS / 8, 256>>>(emb, dists, mask);

    cudaFuncSetAttribute(mlp_kernel, cudaFuncAttributeMaxDynamicSharedMemorySize,
                         SMEM_BYTES);
    mlp_kernel<<<NPTS / MTILE, NTHREADS, SMEM_BYTES>>>(
        b1a, b1b, b3a, b3b, Wa, ba, Wc, bc, vdirs, out);
}

// round 4
// speedup vs baseline: 1.4057x; 1.4057x over previous
#include <cuda_runtime.h>
#include <cuda_bf16.h>

#define NPTS     163840      // B*R*SR
#define KNEI     8
#define FDIM     32
#define HDIM     256
#define EPSV     1e-8f
#define MTILE    128
#define NTHREADS 512
#define AP       264         // act pitch (bf16): 528B rows, 132 words = 4 mod 32 -> ldmatrix conflict-free
#define WPW      72          // weight chunk pitch (bf16): 144B rows, 36 words = 4 mod 32

// ---- smem layout (bytes) ----
#define SM_ACT   0                         // [128][AP] bf16 = 67,584
#define SM_WB    67584                     // 2 x [256][WPW] bf16 = 2 x 36,864
#define SM_BS    (SM_WB + 73728)           // 4 x 256 floats
#define SM_HD    (SM_BS + 4096)            // head weights 256 + 840 floats
#define SMEM_BYTES (SM_HD + 4384)

// -------- device scratch --------
__device__ __nv_bfloat16 g_feat[(size_t)NPTS * FDIM];
__device__ __nv_bfloat16 g_w1a[HDIM * FDIM];    // W^T [out][in] bf16
__device__ __nv_bfloat16 g_w1b[HDIM * HDIM];
__device__ __nv_bfloat16 g_w3a[HDIM * HDIM];
__device__ __nv_bfloat16 g_w3b[HDIM * HDIM];

__device__ __forceinline__ unsigned smem_u32(const void* p) {
    unsigned a;
    asm("{ .reg .u64 t; cvta.to.shared.u64 t, %1; cvt.u32.u64 %0, t; }" : "=r"(a) : "l"(p));
    return a;
}
__device__ __forceinline__ void ldsm4(unsigned& r0, unsigned& r1, unsigned& r2,
                                      unsigned& r3, unsigned addr) {
    asm volatile("ldmatrix.sync.aligned.m8n8.x4.shared.b16 {%0,%1,%2,%3}, [%4];"
                 : "=r"(r0), "=r"(r1), "=r"(r2), "=r"(r3) : "r"(addr));
}
__device__ __forceinline__ void cp16(unsigned dst, const void* src) {
    asm volatile("cp.async.cg.shared.global [%0], [%1], 16;" :: "r"(dst), "l"(src) : "memory");
}
#define CP_COMMIT() asm volatile("cp.async.commit_group;" ::: "memory")

// ============================================================
// Kernel 1: transpose weights [in][out] -> [out][in], cast bf16
// ============================================================
__global__ void convert_weights_kernel(const float* __restrict__ W1a,
                                       const float* __restrict__ W1b,
                                       const float* __restrict__ W3a,
                                       const float* __restrict__ W3b) {
    int idx = blockIdx.x * blockDim.x + threadIdx.x;
    if (idx < HDIM * FDIM) {
        int o = idx / FDIM, i = idx - o * FDIM;
        g_w1a[idx] = __float2bfloat16(W1a[i * HDIM + o]);
    }
    if (idx < HDIM * HDIM) {
        int o = idx / HDIM, i = idx - o * HDIM;
        g_w1b[idx] = __float2bfloat16(W1b[i * HDIM + o]);
        g_w3a[idx] = __float2bfloat16(W3a[i * HDIM + o]);
        g_w3b[idx] = __float2bfloat16(W3b[i * HDIM + o]);
    }
}

// ============================================================
// Kernel 2: aggregation (warp per point)
// ============================================================
__global__ void prep_kernel(const float* __restrict__ emb,
                            const float* __restrict__ dists,
                            const int*   __restrict__ mask) {
    int gw   = (blockIdx.x * blockDim.x + threadIdx.x) >> 5;
    int lane = threadIdx.x & 31;
    if (gw >= NPTS) return;

    float w = 0.f;
    if (lane < KNEI) {
        const float* d = dists + (size_t)gw * (KNEI * 3) + lane * 3;
        float d0 = d[0], d1 = d[1], d2 = d[2];
        float n2 = d0 * d0 + d1 * d1 + d2 * d2;
        w = mask[(size_t)gw * KNEI + lane] ? (1.0f / fmaxf(n2, EPSV)) : 0.f;
    }
    float ws = w;
    #pragma unroll
    for (int o = 16; o > 0; o >>= 1) ws += __shfl_xor_sync(0xffffffffu, ws, o);
    w /= fmaxf(ws, EPSV);

    const float* e = emb + (size_t)gw * (KNEI * FDIM) + lane;
    float acc = 0.f;
    #pragma unroll
    for (int k = 0; k < KNEI; k++) {
        float wk = __shfl_sync(0xffffffffu, w, k);
        acc += wk * e[k * FDIM];
    }
    g_feat[(size_t)gw * FDIM + lane] = __float2bfloat16(acc);
}

// stage one 64-col chunk (or 32-col for layer 1) of W^T[256][K] into a wbuf
__device__ __forceinline__ void stage_chunk(unsigned dst, const __nv_bfloat16* __restrict__ gW,
                                            int K, int c, int scount, int tid) {
    int total = 256 * scount;
    for (int i = tid; i < total; i += NTHREADS) {
        int o = i / scount, s = i - o * scount;
        cp16(dst + o * (WPW * 2) + s * 16, gW + (size_t)o * K + c * 64 + s * 8);
    }
}

// ============================================================
// Kernel 3: fused MLP + heads. 128 rows/CTA, 512 threads, 16 warps 4x4.
// ldmatrix fragments, cp.async double-buffered weight chunks.
// ============================================================
__global__ void __launch_bounds__(NTHREADS, 1)
mlp_kernel(const float* __restrict__ b1a, const float* __restrict__ b1b,
           const float* __restrict__ b3a, const float* __restrict__ b3b,
           const float* __restrict__ Wa,  const float* __restrict__ ba,
           const float* __restrict__ Wc,  const float* __restrict__ bc,
           const float* __restrict__ viewdirs, float* __restrict__ out)
{
    extern __shared__ char smem[];
    unsigned sb = smem_u32(smem);
    int tid = threadIdx.x, lane = tid & 31, wid = tid >> 5;
    int wm = wid >> 2, wn = wid & 3;
    int row0 = blockIdx.x * MTILE;

    // ---- initial staging: feat tile (cp.async) + layer1 weight chunk + biases/heads ----
    {   // feat: 128 rows x 32 bf16 = 512 x 16B
        int r = tid >> 2, s = tid & 3;
        cp16(sb + SM_ACT + r * (AP * 2) + s * 16,
             g_feat + (size_t)(row0 + r) * FDIM + s * 8);
    }
    stage_chunk(sb + SM_WB, g_w1a, FDIM, 0, 4, tid);
    CP_COMMIT();
    if (tid < 256) {
        float* bs = (float*)(smem + SM_BS);
        bs[tid] = b1a[tid]; bs[256 + tid] = b1b[tid];
        bs[512 + tid] = b3a[tid]; bs[768 + tid] = b3b[tid];
        ((float*)(smem + SM_HD))[tid] = Wa[tid];
    }
    for (int i = tid; i < 840; i += NTHREADS)
        ((float*)(smem + SM_HD))[256 + i] = Wc[i];

    // per-lane ldmatrix row pre-offsets
    const int mrow = (lane >> 3) & 1, mcol = lane >> 4, i8 = lane & 7;
    unsigned preA[2], preBr[4];
    #pragma unroll
    for (int mt = 0; mt < 2; mt++) {
        int r = wm * 32 + mt * 16 + mrow * 8 + i8;
        preA[mt] = sb + SM_ACT + r * (AP * 2) + mcol * 16;
    }
    #pragma unroll
    for (int p = 0; p < 4; p++) {
        int n = wn * 64 + p * 16 + mcol * 8 + i8;     // mcol -> n+8, mrow -> k+8
        preBr[p] = n * (WPW * 2) + mrow * 16;
    }
    const int g8 = lane >> 2, tq = lane & 3;

    int g = 0;
    #pragma unroll 1
    for (int L = 0; L < 4; L++) {
        int chunks = (L == 0) ? 1 : 4;
        int ktiles = (L == 0) ? 2 : 4;
        float acc[2][8][4];
        #pragma unroll
        for (int mt = 0; mt < 2; mt++)
            #pragma unroll
            for (int nt = 0; nt < 8; nt++)
                #pragma unroll
                for (int q = 0; q < 4; q++) acc[mt][nt][q] = 0.f;

        #pragma unroll 1
        for (int c = 0; c < chunks; c++, g++) {
            int nxt = g + 1;
            if (nxt < 13) {   // prefetch next chunk into other buffer
                int nl = (nxt <= 4) ? 1 : (nxt <= 8) ? 2 : 3;
                int nc = nxt - ((nl == 1) ? 1 : (nl == 2) ? 5 : 9);
                const __nv_bfloat16* wp = (nl == 1) ? g_w1b : (nl == 2) ? g_w3a : g_w3b;
                stage_chunk(sb + SM_WB + (nxt & 1) * (256 * WPW * 2), wp, HDIM, nc, 8, tid);
                CP_COMMIT();
                asm volatile("cp.async.wait_group 1;" ::: "memory");
            } else {
                asm volatile("cp.async.wait_group 0;" ::: "memory");
            }
            __syncthreads();

            unsigned wb = sb + SM_WB + (g & 1) * (256 * WPW * 2);
            int cbase = c * 64;
            #pragma unroll
            for (int kt = 0; kt < 4; kt++) {
                if (kt >= ktiles) break;
                unsigned ca = (cbase + kt * 16) * 2, cw = kt * 32;
                unsigned a[2][4], b[8][2];
                ldsm4(a[0][0], a[0][1], a[0][2], a[0][3], preA[0] + ca);
                ldsm4(a[1][0], a[1][1], a[1][2], a[1][3], preA[1] + ca);
                ldsm4(b[0][0], b[0][1], b[1][0], b[1][1], wb + preBr[0] + cw);
                ldsm4(b[2][0], b[2][1], b[3][0], b[3][1], wb + preBr[1] + cw);
                ldsm4(b[4][0], b[4][1], b[5][0], b[5][1], wb + preBr[2] + cw);
                ldsm4(b[6][0], b[6][1], b[7][0], b[7][1], wb + preBr[3] + cw);
                #pragma unroll
                for (int mt = 0; mt < 2; mt++)
                    #pragma unroll
                    for (int nt = 0; nt < 8; nt++)
                        asm volatile(
                            "mma.sync.aligned.m16n8k16.row.col.f32.bf16.bf16.f32 "
                            "{%0,%1,%2,%3}, {%4,%5,%6,%7}, {%8,%9}, {%0,%1,%2,%3};\n"
                            : "+f"(acc[mt][nt][0]), "+f"(acc[mt][nt][1]),
                              "+f"(acc[mt][nt][2]), "+f"(acc[mt][nt][3])
                            : "r"(a[mt][0]), "r"(a[mt][1]), "r"(a[mt][2]), "r"(a[mt][3]),
                              "r"(b[nt][0]), "r"(b[nt][1]));
            }
        }
        __syncthreads();   // all mma reads of act done before in-place epilogue

        const float* bs = (const float*)(smem + SM_BS) + L * 256;
        __nv_bfloat16* act = (__nv_bfloat16*)(smem + SM_ACT);
        #pragma unroll
        for (int mt = 0; mt < 2; mt++) {
            int r = wm * 32 + mt * 16 + g8;
            #pragma unroll
            for (int nt = 0; nt < 8; nt++) {
                int col = wn * 64 + nt * 8 + tq * 2;
                float bz0 = bs[col], bz1 = bs[col + 1];
                *(__nv_bfloat162*)(act + r * AP + col) = __floats2bfloat162_rn(
                    fmaxf(acc[mt][nt][0] + bz0, 0.f), fmaxf(acc[mt][nt][1] + bz1, 0.f));
                *(__nv_bfloat162*)(act + (r + 8) * AP + col) = __floats2bfloat162_rn(
                    fmaxf(acc[mt][nt][2] + bz0, 0.f), fmaxf(acc[mt][nt][3] + bz1, 0.f));
            }
        }
        // no trailing barrier: next iteration's post-wait __syncthreads orders
        // these writes before the next layer's ldmatrix reads
    }
    __syncthreads();

    // ---- heads: alpha (256->1) + color (280->3), fp32, 2 threads/row ----
    int r = tid >> 1, t = tid & 1;
    if (r < MTILE) {
        const __nv_bfloat16* ar = (const __nv_bfloat16*)(smem + SM_ACT) + r * AP;
        const float* hWa = (const float*)(smem + SM_HD);
        const float* hWc = hWa + 256;                    // [280][3]
        float sa = 0.f, c0 = 0.f, c1 = 0.f, c2 = 0.f;
        for (int k = t * 128; k < t * 128 + 128; k++) {
            float h = __bfloat162float(ar[k]);
            sa += h * hWa[k];
            c0 += h * hWc[k * 3 + 0];
            c1 += h * hWc[k * 3 + 1];
            c2 += h * hWc[k * 3 + 2];
        }
        if (t == 0) {   // viewdir PE, exact fp32
            const float* v = viewdirs + (size_t)(row0 + r) * 3;
            float vx = v[0], vy = v[1], vz = v[2];
            float inv = 1.f / fmaxf(sqrtf(vx * vx + vy * vy + vz * vz), EPSV);
            vx *= inv; vy *= inv; vz *= inv;
            #pragma unroll
            for (int i = 0; i < 4; i++) {
                float f = (float)(1 << i);
                float pe[6];
                pe[0] = sinf(vx * f); pe[1] = sinf(vy * f); pe[2] = sinf(vz * f);
                pe[3] = cosf(vx * f); pe[4] = cosf(vy * f); pe[5] = cosf(vz * f);
                #pragma unroll
                for (int j = 0; j < 6; j++) {
                    const float* wr = hWc + (HDIM + i * 6 + j) * 3;
                    c0 += pe[j] * wr[0]; c1 += pe[j] * wr[1]; c2 += pe[j] * wr[2];
                }
            }
        }
        sa += __shfl_xor_sync(0xffffffffu, sa, 1);
        c0 += __shfl_xor_sync(0xffffffffu, c0, 1);
        c1 += __shfl_xor_sync(0xffffffffu, c1, 1);
        c2 += __shfl_xor_sync(0xffffffffu, c2, 1);
        if (t == 0) {
            float apre  = sa + ba[0] - 1.0f;
            float alpha = (apre > 20.f) ? apre : log1pf(expf(apre));
            float r0 = c0 + bc[0], r1 = c1 + bc[1], r2 = c2 + bc[2];
            const float sc = 1.0f + 2e-3f, sh = 1e-3f;
            float4 o4;
            o4.x = alpha;
            o4.y = sc / (1.f + expf(-r0)) - sh;
            o4.z = sc / (1.f + expf(-r1)) - sh;
            o4.w = sc / (1.f + expf(-r2)) - sh;
            *(float4*)(out + (size_t)(row0 + r) * 4) = o4;
        }
    }
}

// ============================================================
extern "C" void kernel_launch(void* const* d_in, const int* in_sizes, int n_in,
                              void* d_out, int out_size) {
    const float* emb   = (const float*)d_in[0];
    const float* dists = (const float*)d_in[1];
    const float* vdirs = (const float*)d_in[2];
    const int*   mask  = (const int*)d_in[3];
    const float* W1a = (const float*)d_in[4];
    const float* b1a = (const float*)d_in[5];
    const float* W1b = (const float*)d_in[6];
    const float* b1b = (const float*)d_in[7];
    const float* W3a = (const float*)d_in[8];
    const float* b3a = (const float*)d_in[9];
    const float* W3b = (const float*)d_in[10];
    const float* b3b = (const float*)d_in[11];
    const float* Wa  = (const float*)d_in[12];
    const float* ba  = (const float*)d_in[13];
    const float* Wc  = (const float*)d_in[14];
    const float* bc  = (const float*)d_in[15];
    float* out = (float*)d_out;

    convert_weights_kernel<<<(HDIM * HDIM + 255) / 256, 256>>>(W1a, W1b, W3a, W3b);
    prep_kernel<<<NPTS / 8, 256>>>(emb, dists, mask);

    cudaFuncSetAttribute(mlp_kernel, cudaFuncAttributeMaxDynamicSharedMemorySize,
                         SMEM_BYTES);
    mlp_kernel<<<NPTS / MTILE, NTHREADS, SMEM_BYTES>>>(
        b1a, b1b, b3a, b3b, Wa, ba, Wc, bc, vdirs, out);
}